// round 15
// baseline (speedup 1.0000x reference)
#include <cuda_runtime.h>
#include <math.h>

#define NROWS 65536
#define K1 512
#define A3C 64
#define CW 16
#define DT 8
#define PPC 96
#define NBLK_COV 256         // blocks in covariance pass (256 rows each)

// ---------------- scratch (device globals; no runtime allocation) -------------
__device__ float g_t[(size_t)NROWS * A3C];              // normalized t   16 MB
__device__ float g_y[(size_t)DT * NROWS * PPC];         // tower outputs 201 MB
__device__ float g_cp[(size_t)NBLK_COV * A3C * A3C];    // C partials      4 MB
__device__ float g_cm[(size_t)NBLK_COV * A3C];          // m partials
__device__ float g_C[A3C * A3C];                        // C = rep^T rep (sums)
__device__ float g_m[A3C];                              // column sums
__device__ float g_scale[DT * A3C];                     // gamma * rsqrt(var+eps)
__device__ float g_shift[DT * A3C];                     // beta - E[g]*scale

// ---------------- kernel 1: t = normalize(x @ B), double-buffered (proven) ---
#define K1_BUFSZ (32 * 129 + 32 * 64)       // 6176 floats
#define K1_DSMEM (2 * K1_BUFSZ * 4)
__global__ __launch_bounds__(256) void k1_gemm_norm(const float* __restrict__ x,
                                                    const float* __restrict__ B) {
    extern __shared__ __align__(16) float k1sm[];
    __shared__ float invs[128];
    int tid = threadIdx.x;
    int tx = tid & 7, ty = tid >> 3;
    int n0 = blockIdx.x * 128;

    int lr = tid >> 3, lk4 = tid & 7;
    int lkk = tid >> 4, lc4 = tid & 15;

    float acc[4][8];
#pragma unroll
    for (int j = 0; j < 4; j++)
#pragma unroll
        for (int c = 0; c < 8; c++) acc[j][c] = 0.f;

    float4 xv[4], bv[2];
#pragma unroll
    for (int i = 0; i < 4; i++)
        xv[i] = *(const float4*)(x + (size_t)(n0 + lr + i * 32) * K1 + lk4 * 4);
#pragma unroll
    for (int i = 0; i < 2; i++)
        bv[i] = *(const float4*)(B + (size_t)(lkk + i * 16) * 64 + lc4 * 4);
    {
        float* Xs = k1sm;
        float* Bs = k1sm + 4128;
#pragma unroll
        for (int i = 0; i < 4; i++) {
            Xs[(lk4 * 4 + 0) * 129 + lr + i * 32] = xv[i].x;
            Xs[(lk4 * 4 + 1) * 129 + lr + i * 32] = xv[i].y;
            Xs[(lk4 * 4 + 2) * 129 + lr + i * 32] = xv[i].z;
            Xs[(lk4 * 4 + 3) * 129 + lr + i * 32] = xv[i].w;
        }
#pragma unroll
        for (int i = 0; i < 2; i++)
            *(float4*)(Bs + (lkk + i * 16) * 64 + lc4 * 4) = bv[i];
    }
    __syncthreads();

    for (int kt = 0; kt < 16; kt++) {
        if (kt < 15) {
            int k0 = (kt + 1) * 32;
#pragma unroll
            for (int i = 0; i < 4; i++)
                xv[i] = *(const float4*)(x + (size_t)(n0 + lr + i * 32) * K1 + k0 + lk4 * 4);
#pragma unroll
            for (int i = 0; i < 2; i++)
                bv[i] = *(const float4*)(B + (size_t)(k0 + lkk + i * 16) * 64 + lc4 * 4);
        }
        const float* Xs = k1sm + (kt & 1) * K1_BUFSZ;
        const float* Bs = Xs + 4128;
#pragma unroll
        for (int kk = 0; kk < 32; kk++) {
            float ar[4];
#pragma unroll
            for (int j = 0; j < 4; j++) ar[j] = Xs[kk * 129 + ty * 4 + j];
            float4 b0 = *(const float4*)(Bs + kk * 64 + tx * 8);
            float4 b1 = *(const float4*)(Bs + kk * 64 + tx * 8 + 4);
#pragma unroll
            for (int j = 0; j < 4; j++) {
                acc[j][0] += ar[j] * b0.x; acc[j][1] += ar[j] * b0.y;
                acc[j][2] += ar[j] * b0.z; acc[j][3] += ar[j] * b0.w;
                acc[j][4] += ar[j] * b1.x; acc[j][5] += ar[j] * b1.y;
                acc[j][6] += ar[j] * b1.z; acc[j][7] += ar[j] * b1.w;
            }
        }
        if (kt < 15) {
            float* Xw = k1sm + ((kt + 1) & 1) * K1_BUFSZ;
            float* Bw = Xw + 4128;
#pragma unroll
            for (int i = 0; i < 4; i++) {
                Xw[(lk4 * 4 + 0) * 129 + lr + i * 32] = xv[i].x;
                Xw[(lk4 * 4 + 1) * 129 + lr + i * 32] = xv[i].y;
                Xw[(lk4 * 4 + 2) * 129 + lr + i * 32] = xv[i].z;
                Xw[(lk4 * 4 + 3) * 129 + lr + i * 32] = xv[i].w;
            }
#pragma unroll
            for (int i = 0; i < 2; i++)
                *(float4*)(Bw + (lkk + i * 16) * 64 + lc4 * 4) = bv[i];
            __syncthreads();
        }
    }
    float* ps = k1sm;
#pragma unroll
    for (int j = 0; j < 4; j++) {
        float s = 0.f;
#pragma unroll
        for (int c = 0; c < 8; c++) s += acc[j][c] * acc[j][c];
        ps[(ty * 4 + j) * 8 + tx] = s;
    }
    __syncthreads();
    if (tid < 128) {
        float s = 0.f;
#pragma unroll
        for (int q = 0; q < 8; q++) s += ps[tid * 8 + q];
        invs[tid] = 1.f / fmaxf(sqrtf(s), 1e-12f);
    }
    __syncthreads();
#pragma unroll
    for (int j = 0; j < 4; j++) {
        int r = ty * 4 + j;
        float inv = invs[r];
        float4 o0, o1;
        o0.x = acc[j][0] * inv; o0.y = acc[j][1] * inv; o0.z = acc[j][2] * inv; o0.w = acc[j][3] * inv;
        o1.x = acc[j][4] * inv; o1.y = acc[j][5] * inv; o1.z = acc[j][6] * inv; o1.w = acc[j][7] * inv;
        *(float4*)(g_t + (size_t)(n0 + r) * 64 + tx * 8)     = o0;
        *(float4*)(g_t + (size_t)(n0 + r) * 64 + tx * 8 + 4) = o1;
    }
}

// ---------------- kernel 2: windowed affine sum -> rep  (proven) -------------
__global__ __launch_bounds__(256) void k2_window(const float* __restrict__ lw,
                                                 const float* __restrict__ lb,
                                                 float* __restrict__ rep) {
    __shared__ float ts[143 * 64];
    int tid = threadIdx.x;
    int a = tid & 63, rg = tid >> 6;
    int R0 = blockIdx.x * 128;

    for (int l = tid; l < 143 * 64; l += 256) {
        int s = l >> 6, aa = l & 63;
        int g = R0 - 15 + s;
        ts[l] = (g >= 0) ? g_t[(size_t)g * 64 + aa] : 0.f;
    }
    float w[CW];
    float bs = 0.f;
#pragma unroll
    for (int j = 0; j < CW; j++) { w[j] = lw[j * 64 + a]; bs += lb[j * 64 + a]; }
    __syncthreads();

    for (int m = 0; m < 32; m++) {
        int r = m * 4 + rg;
        int i = R0 + r;
        float acc = bs;
        if (i >= CW - 1) {
#pragma unroll
            for (int j = 0; j < CW; j++) acc += w[j] * ts[(r + j) * 64 + a];
        } else {
#pragma unroll
            for (int j = 0; j < CW; j++) {
                int g = min(j, i);
                acc += w[j] * ts[(g + 15) * 64 + a];
            }
        }
        rep[(size_t)i * 64 + a] = acc;
    }
}

// ---------------- kernel 3c: C = rep^T rep partials + column sums ------------
__global__ __launch_bounds__(256) void k3_cov(const float* __restrict__ rep) {
    __shared__ __align__(16) float ts[32 * 68];
    int tid = threadIdx.x;
    int p = tid >> 4, q = tid & 15;
    int a0 = p * 4, b0 = q * 4;
    size_t R0 = (size_t)blockIdx.x * 256;

    float acc[4][4];
#pragma unroll
    for (int i = 0; i < 4; i++)
#pragma unroll
        for (int j = 0; j < 4; j++) acc[i][j] = 0.f;
    float msum = 0.f;

    for (int chunk = 0; chunk < 8; chunk++) {
#pragma unroll
        for (int i = 0; i < 2; i++) {
            int idx = tid + i * 256;            // 0..511 float4s
            int row = idx >> 4, c4 = idx & 15;
            float4 v = *(const float4*)(rep + (R0 + chunk * 32 + row) * 64 + c4 * 4);
            *(float4*)(ts + row * 68 + c4 * 4) = v;
        }
        __syncthreads();
#pragma unroll 4
        for (int k = 0; k < 32; k++) {
            float4 ta = *(const float4*)(ts + k * 68 + a0);
            float4 tb = *(const float4*)(ts + k * 68 + b0);
            acc[0][0] += ta.x * tb.x; acc[0][1] += ta.x * tb.y; acc[0][2] += ta.x * tb.z; acc[0][3] += ta.x * tb.w;
            acc[1][0] += ta.y * tb.x; acc[1][1] += ta.y * tb.y; acc[1][2] += ta.y * tb.z; acc[1][3] += ta.y * tb.w;
            acc[2][0] += ta.z * tb.x; acc[2][1] += ta.z * tb.y; acc[2][2] += ta.z * tb.z; acc[2][3] += ta.z * tb.w;
            acc[3][0] += ta.w * tb.x; acc[3][1] += ta.w * tb.y; acc[3][2] += ta.w * tb.z; acc[3][3] += ta.w * tb.w;
        }
        if (tid < 64) {
#pragma unroll 8
            for (int k = 0; k < 32; k++) msum += ts[k * 68 + tid];
        }
        __syncthreads();
    }
    float* cp = g_cp + (size_t)blockIdx.x * 4096;
#pragma unroll
    for (int i = 0; i < 4; i++)
#pragma unroll
        for (int j = 0; j < 4; j++)
            cp[(a0 + i) * 64 + (b0 + j)] = acc[i][j];
    if (tid < 64) g_cm[(size_t)blockIdx.x * 64 + tid] = msum;
}

// ---------------- kernel 4a: reduce partials -> g_C, g_m  (65-block, proven) -
__global__ __launch_bounds__(256) void k4a_reduce() {
    __shared__ float red[256];
    int tid = threadIdx.x;
    int i = tid & 63, part = tid >> 6;
    int blk = blockIdx.x;
    float s = 0.f;
    if (blk < 64) {
        int idx = blk * 64 + i;
        for (int pb = part * 64; pb < part * 64 + 64; pb++)
            s += g_cp[(size_t)pb * 4096 + idx];
    } else {
        for (int pb = part * 64; pb < part * 64 + 64; pb++)
            s += g_cm[(size_t)pb * 64 + i];
    }
    red[tid] = s;
    __syncthreads();
    if (part == 0) {
        float t = red[i] + red[i + 64] + red[i + 128] + red[i + 192];
        if (blk < 64) g_C[blk * 64 + i] = t;
        else          g_m[i] = t;
    }
}

// ---------------- kernel 4b: analytic BN scale/shift per (d,b)  (proven) -----
__global__ __launch_bounds__(256) void k4b_stats(const float* __restrict__ W1,
                                                 const float* __restrict__ gamma,
                                                 const float* __restrict__ beta) {
    __shared__ float Cs[64 * 65];
    __shared__ float Ws1[4096];
    __shared__ float sm_m[64];
    __shared__ float mq[256], me[256];
    int tid = threadIdx.x;
    int b = tid & 63, part = tid >> 6;
    int d = blockIdx.x;

    for (int idx = tid; idx < 4096; idx += 256) {
        int a = idx >> 6, a2 = idx & 63;
        Cs[a * 65 + a2] = g_C[idx];
        Ws1[idx] = W1[(size_t)d * 4096 + idx];
    }
    if (tid < 64) sm_m[tid] = g_m[tid];
    __syncthreads();

    float qp = 0.f, ep = 0.f;
    int aBeg = part * 16;
#pragma unroll 2
    for (int a = aBeg; a < aBeg + 16; a++) {
        float wa = Ws1[a * 64 + b];
        float ta = 0.f;
#pragma unroll 8
        for (int a2 = 0; a2 < 64; a2++) ta += Cs[a * 65 + a2] * Ws1[a2 * 64 + b];
        qp += wa * ta;
        ep += sm_m[a] * wa;
    }
    mq[tid] = qp; me[tid] = ep;
    __syncthreads();
    if (part == 0) {
        const float invN = 1.f / 65536.f;
        float q  = mq[b] + mq[b + 64] + mq[b + 128] + mq[b + 192];
        float eg = (me[b] + me[b + 64] + me[b + 128] + me[b + 192]) * invN;
        float var = q * invN - eg * eg;
        float sc = gamma[d * 64 + b] * rsqrtf(fmaxf(var, 0.f) + 1e-5f);
        g_scale[d * 64 + b] = sc;
        g_shift[d * 64 + b] = beta[d * 64 + b] - eg * sc;
    }
}

// ---------------- kernel 5f: fused  g=rep@W1 -> BN+ELU -> y=h'@W2+b2 ---------
// R14 structure + fast ELU (__expf) + W2/b2 load hoisting to hide latency.
#define HSTR 129
#define K5_DSMEM ((6144 + 64 * HSTR) * 4)
__global__ __launch_bounds__(256) void k5_fused(const float* __restrict__ rep,
                                               const float* __restrict__ W1,
                                               const float* __restrict__ W2,
                                               const float* __restrict__ b2) {
    extern __shared__ __align__(16) float dsm[];
    float* Ws = dsm;            // 6144 floats
    float* HR = dsm + 6144;     // 64*129 floats
    int tid = threadIdx.x;
    int tx = tid & 7, ty = tid >> 3;
    int d = blockIdx.y;
    int n0 = blockIdx.x * 128;

    float sc[8], sh[8];
#pragma unroll
    for (int c = 0; c < 8; c++) {
        sc[c] = g_scale[d * 64 + tx * 8 + c];
        sh[c] = g_shift[d * 64 + tx * 8 + c];
    }

    // ---- stage FULL rep tile k-major ----
#pragma unroll
    for (int half = 0; half < 2; half++) {
#pragma unroll
        for (int i = 0; i < 4; i++) {
            int l = tid + i * 256;
            int r = l >> 3, kk4 = l & 7;
            float4 v = *(const float4*)(rep + (size_t)(n0 + r) * 64 + half * 32 + kk4 * 4);
            int kb = half * 32 + kk4 * 4;
            HR[(kb + 0) * HSTR + r] = v.x;
            HR[(kb + 1) * HSTR + r] = v.y;
            HR[(kb + 2) * HSTR + r] = v.z;
            HR[(kb + 3) * HSTR + r] = v.w;
        }
    }
    // ---- stage FULL W1 ----
#pragma unroll
    for (int i = 0; i < 4; i++) {
        int l = tid + i * 256;
        *(float4*)(Ws + l * 4) = *(const float4*)(W1 + (size_t)d * 4096 + l * 4);
    }
    __syncthreads();                                   // sync #1

    float acc[4][8];
#pragma unroll
    for (int j = 0; j < 4; j++)
#pragma unroll
        for (int c = 0; c < 8; c++) acc[j][c] = 0.f;
#pragma unroll 8
    for (int kk = 0; kk < 64; kk++) {
        float ar[4];
#pragma unroll
        for (int j = 0; j < 4; j++) ar[j] = HR[kk * HSTR + ty * 4 + j];
        float4 w0 = *(const float4*)(Ws + kk * 64 + tx * 8);
        float4 w1 = *(const float4*)(Ws + kk * 64 + tx * 8 + 4);
#pragma unroll
        for (int j = 0; j < 4; j++) {
            acc[j][0] += ar[j] * w0.x; acc[j][1] += ar[j] * w0.y;
            acc[j][2] += ar[j] * w0.z; acc[j][3] += ar[j] * w0.w;
            acc[j][4] += ar[j] * w1.x; acc[j][5] += ar[j] * w1.y;
            acc[j][6] += ar[j] * w1.z; acc[j][7] += ar[j] * w1.w;
        }
    }
    __syncthreads();                                   // sync #2

    // issue W2 loads NOW (into regs) — latency hides under the h' write phase
    float4 w2r[6];
#pragma unroll
    for (int i = 0; i < 6; i++)
        w2r[i] = *(const float4*)(W2 + (size_t)d * 6144 + (tid + i * 256) * 4);

    // ---- BN + fast ELU, h' k-major into HR (2-way max conflicts) ----
#pragma unroll
    for (int c = 0; c < 8; c++)
#pragma unroll
        for (int j = 0; j < 4; j++) {
            float v = acc[j][c] * sc[c] + sh[c];
            v = v > 0.f ? v : (__expf(v) - 1.f);
            HR[(tx * 8 + c) * HSTR + ty * 4 + j] = v;
        }
    // park prefetched W2 into smem
#pragma unroll
    for (int i = 0; i < 6; i++)
        *(float4*)(Ws + (tid + i * 256) * 4) = w2r[i];
    __syncthreads();                                   // sync #3

    int tx2 = tid & 15, ty2 = tid >> 4;
    // hoist b2 — latency hides under GEMM2
    float bb[6];
#pragma unroll
    for (int c = 0; c < 6; c++) bb[c] = b2[d * 96 + tx2 * 6 + c];

    float acc2[8][6];
#pragma unroll
    for (int j = 0; j < 8; j++)
#pragma unroll
        for (int c = 0; c < 6; c++) acc2[j][c] = 0.f;
#pragma unroll 8
    for (int kk = 0; kk < 64; kk++) {
        float ar[8];
#pragma unroll
        for (int j = 0; j < 8; j++) ar[j] = HR[kk * HSTR + ty2 * 8 + j];
        const float* wp = Ws + kk * 96 + tx2 * 6;
        float2 w0 = *(const float2*)(wp);
        float2 w1 = *(const float2*)(wp + 2);
        float2 w2v = *(const float2*)(wp + 4);
#pragma unroll
        for (int j = 0; j < 8; j++) {
            acc2[j][0] += ar[j] * w0.x;  acc2[j][1] += ar[j] * w0.y;
            acc2[j][2] += ar[j] * w1.x;  acc2[j][3] += ar[j] * w1.y;
            acc2[j][4] += ar[j] * w2v.x; acc2[j][5] += ar[j] * w2v.y;
        }
    }
#pragma unroll
    for (int j = 0; j < 8; j++) {
        int r = ty2 * 8 + j;
        float* op = g_y + (size_t)d * NROWS * 96 + (size_t)(n0 + r) * 96 + tx2 * 6;
        float2 o;
        o.x = acc2[j][0] + bb[0]; o.y = acc2[j][1] + bb[1]; *(float2*)(op)     = o;
        o.x = acc2[j][2] + bb[2]; o.y = acc2[j][3] + bb[3]; *(float2*)(op + 2) = o;
        o.x = acc2[j][4] + bb[4]; o.y = acc2[j][5] + bb[5]; *(float2*)(op + 4) = o;
    }
}

// ---------------- kernel 6: interleave, float4 everywhere  (proven) ----------
__global__ __launch_bounds__(256) void k6_interleave(float* __restrict__ out) {
    __shared__ __align__(16) float sm[8 * 772];
    int tid = threadIdx.x;
    int n0 = blockIdx.x * 8;
#pragma unroll
    for (int i = 0; i < 6; i++) {
        int idx = tid + i * 256;            // 0..1535 float4s
        int f = idx * 4;
        int d = f / 768; int m = f % 768; int n = m / 96; int p = m % 96;
        float4 v = *(const float4*)(g_y + (size_t)d * NROWS * 96 + (size_t)(n0 + n) * 96 + p);
        *(float4*)(sm + d * 772 + n * 96 + p) = v;
    }
    __syncthreads();
#pragma unroll
    for (int i = 0; i < 6; i++) {
        int idx = tid + i * 256;
        int f = idx * 4;
        int n = f / 768; int q = f % 768;
        int p = q >> 3; int dd = q & 7;
        float4 o;
        o.x = sm[(dd + 0) * 772 + n * 96 + p];
        o.y = sm[(dd + 1) * 772 + n * 96 + p];
        o.z = sm[(dd + 2) * 772 + n * 96 + p];
        o.w = sm[(dd + 3) * 772 + n * 96 + p];
        *(float4*)(out + (size_t)(n0 + n) * 768 + q) = o;
    }
}

// ---------------- launcher ----------------------------------------------------
extern "C" void kernel_launch(void* const* d_in, const int* in_sizes, int n_in,
                              void* d_out, int out_size) {
    const float* x     = (const float*)d_in[0];
    const float* B     = (const float*)d_in[1];
    const float* lw    = (const float*)d_in[2];
    const float* lb    = (const float*)d_in[3];
    const float* W1    = (const float*)d_in[4];
    // d_in[5] = b1: cancels exactly inside train-mode BatchNorm (h - mu); unused.
    const float* gamma = (const float*)d_in[6];
    const float* beta  = (const float*)d_in[7];
    const float* W2    = (const float*)d_in[8];
    const float* b2    = (const float*)d_in[9];

    float* out = (float*)d_out;
    float* rep = out + (size_t)NROWS * (PPC * DT);   // rep section after y_1

    cudaFuncSetAttribute(k1_gemm_norm, cudaFuncAttributeMaxDynamicSharedMemorySize, K1_DSMEM);
    cudaFuncSetAttribute(k5_fused, cudaFuncAttributeMaxDynamicSharedMemorySize, K5_DSMEM);

    k1_gemm_norm<<<512, 256, K1_DSMEM>>>(x, B);
    k2_window<<<512, 256>>>(lw, lb, rep);
    k3_cov<<<NBLK_COV, 256>>>(rep);
    k4a_reduce<<<65, 256>>>();
    k4b_stats<<<DT, 256>>>(W1, gamma, beta);
    k5_fused<<<dim3(512, DT), 256, K5_DSMEM>>>(rep, W1, W2, b2);
    k6_interleave<<<8192, 256>>>(out);
}

// round 16
// speedup vs baseline: 1.5691x; 1.5691x over previous
#include <cuda_runtime.h>
#include <math.h>

#define NROWS 65536
#define K1 512
#define A3C 64
#define CW 16
#define DT 8
#define PPC 96
#define NBLK_COV 256         // blocks in covariance pass (256 rows each)

// ---------------- scratch (device globals; no runtime allocation) -------------
__device__ float g_t[(size_t)NROWS * A3C];              // normalized t   16 MB
__device__ float g_y[(size_t)DT * NROWS * PPC];         // tower outputs 201 MB
__device__ float g_cp[(size_t)NBLK_COV * A3C * A3C];    // C partials      4 MB
__device__ float g_cm[(size_t)NBLK_COV * A3C];          // m partials
__device__ float g_C[A3C * A3C];                        // C = rep^T rep (sums)
__device__ float g_m[A3C];                              // column sums
__device__ float g_scale[DT * A3C];                     // gamma * rsqrt(var+eps)
__device__ float g_shift[DT * A3C];                     // beta - E[g]*scale

// ---------------- kernel 1: t = normalize(x @ B), double-buffered (proven) ---
#define K1_BUFSZ (32 * 129 + 32 * 64)       // 6176 floats
#define K1_DSMEM (2 * K1_BUFSZ * 4)
__global__ __launch_bounds__(256) void k1_gemm_norm(const float* __restrict__ x,
                                                    const float* __restrict__ B) {
    extern __shared__ __align__(16) float k1sm[];
    __shared__ float invs[128];
    int tid = threadIdx.x;
    int tx = tid & 7, ty = tid >> 3;
    int n0 = blockIdx.x * 128;

    int lr = tid >> 3, lk4 = tid & 7;
    int lkk = tid >> 4, lc4 = tid & 15;

    float acc[4][8];
#pragma unroll
    for (int j = 0; j < 4; j++)
#pragma unroll
        for (int c = 0; c < 8; c++) acc[j][c] = 0.f;

    float4 xv[4], bv[2];
#pragma unroll
    for (int i = 0; i < 4; i++)
        xv[i] = *(const float4*)(x + (size_t)(n0 + lr + i * 32) * K1 + lk4 * 4);
#pragma unroll
    for (int i = 0; i < 2; i++)
        bv[i] = *(const float4*)(B + (size_t)(lkk + i * 16) * 64 + lc4 * 4);
    {
        float* Xs = k1sm;
        float* Bs = k1sm + 4128;
#pragma unroll
        for (int i = 0; i < 4; i++) {
            Xs[(lk4 * 4 + 0) * 129 + lr + i * 32] = xv[i].x;
            Xs[(lk4 * 4 + 1) * 129 + lr + i * 32] = xv[i].y;
            Xs[(lk4 * 4 + 2) * 129 + lr + i * 32] = xv[i].z;
            Xs[(lk4 * 4 + 3) * 129 + lr + i * 32] = xv[i].w;
        }
#pragma unroll
        for (int i = 0; i < 2; i++)
            *(float4*)(Bs + (lkk + i * 16) * 64 + lc4 * 4) = bv[i];
    }
    __syncthreads();

    for (int kt = 0; kt < 16; kt++) {
        if (kt < 15) {
            int k0 = (kt + 1) * 32;
#pragma unroll
            for (int i = 0; i < 4; i++)
                xv[i] = *(const float4*)(x + (size_t)(n0 + lr + i * 32) * K1 + k0 + lk4 * 4);
#pragma unroll
            for (int i = 0; i < 2; i++)
                bv[i] = *(const float4*)(B + (size_t)(k0 + lkk + i * 16) * 64 + lc4 * 4);
        }
        const float* Xs = k1sm + (kt & 1) * K1_BUFSZ;
        const float* Bs = Xs + 4128;
#pragma unroll
        for (int kk = 0; kk < 32; kk++) {
            float ar[4];
#pragma unroll
            for (int j = 0; j < 4; j++) ar[j] = Xs[kk * 129 + ty * 4 + j];
            float4 b0 = *(const float4*)(Bs + kk * 64 + tx * 8);
            float4 b1 = *(const float4*)(Bs + kk * 64 + tx * 8 + 4);
#pragma unroll
            for (int j = 0; j < 4; j++) {
                acc[j][0] += ar[j] * b0.x; acc[j][1] += ar[j] * b0.y;
                acc[j][2] += ar[j] * b0.z; acc[j][3] += ar[j] * b0.w;
                acc[j][4] += ar[j] * b1.x; acc[j][5] += ar[j] * b1.y;
                acc[j][6] += ar[j] * b1.z; acc[j][7] += ar[j] * b1.w;
            }
        }
        if (kt < 15) {
            float* Xw = k1sm + ((kt + 1) & 1) * K1_BUFSZ;
            float* Bw = Xw + 4128;
#pragma unroll
            for (int i = 0; i < 4; i++) {
                Xw[(lk4 * 4 + 0) * 129 + lr + i * 32] = xv[i].x;
                Xw[(lk4 * 4 + 1) * 129 + lr + i * 32] = xv[i].y;
                Xw[(lk4 * 4 + 2) * 129 + lr + i * 32] = xv[i].z;
                Xw[(lk4 * 4 + 3) * 129 + lr + i * 32] = xv[i].w;
            }
#pragma unroll
            for (int i = 0; i < 2; i++)
                *(float4*)(Bw + (lkk + i * 16) * 64 + lc4 * 4) = bv[i];
            __syncthreads();
        }
    }
    float* ps = k1sm;
#pragma unroll
    for (int j = 0; j < 4; j++) {
        float s = 0.f;
#pragma unroll
        for (int c = 0; c < 8; c++) s += acc[j][c] * acc[j][c];
        ps[(ty * 4 + j) * 8 + tx] = s;
    }
    __syncthreads();
    if (tid < 128) {
        float s = 0.f;
#pragma unroll
        for (int q = 0; q < 8; q++) s += ps[tid * 8 + q];
        invs[tid] = 1.f / fmaxf(sqrtf(s), 1e-12f);
    }
    __syncthreads();
#pragma unroll
    for (int j = 0; j < 4; j++) {
        int r = ty * 4 + j;
        float inv = invs[r];
        float4 o0, o1;
        o0.x = acc[j][0] * inv; o0.y = acc[j][1] * inv; o0.z = acc[j][2] * inv; o0.w = acc[j][3] * inv;
        o1.x = acc[j][4] * inv; o1.y = acc[j][5] * inv; o1.z = acc[j][6] * inv; o1.w = acc[j][7] * inv;
        *(float4*)(g_t + (size_t)(n0 + r) * 64 + tx * 8)     = o0;
        *(float4*)(g_t + (size_t)(n0 + r) * 64 + tx * 8 + 4) = o1;
    }
}

// ---------------- kernel 2: windowed affine sum -> rep  (proven) -------------
__global__ __launch_bounds__(256) void k2_window(const float* __restrict__ lw,
                                                 const float* __restrict__ lb,
                                                 float* __restrict__ rep) {
    __shared__ float ts[143 * 64];
    int tid = threadIdx.x;
    int a = tid & 63, rg = tid >> 6;
    int R0 = blockIdx.x * 128;

    for (int l = tid; l < 143 * 64; l += 256) {
        int s = l >> 6, aa = l & 63;
        int g = R0 - 15 + s;
        ts[l] = (g >= 0) ? g_t[(size_t)g * 64 + aa] : 0.f;
    }
    float w[CW];
    float bs = 0.f;
#pragma unroll
    for (int j = 0; j < CW; j++) { w[j] = lw[j * 64 + a]; bs += lb[j * 64 + a]; }
    __syncthreads();

    for (int m = 0; m < 32; m++) {
        int r = m * 4 + rg;
        int i = R0 + r;
        float acc = bs;
        if (i >= CW - 1) {
#pragma unroll
            for (int j = 0; j < CW; j++) acc += w[j] * ts[(r + j) * 64 + a];
        } else {
#pragma unroll
            for (int j = 0; j < CW; j++) {
                int g = min(j, i);
                acc += w[j] * ts[(g + 15) * 64 + a];
            }
        }
        rep[(size_t)i * 64 + a] = acc;
    }
}

// ---------------- kernel 3c: C = rep^T rep partials + column sums ------------
__global__ __launch_bounds__(256) void k3_cov(const float* __restrict__ rep) {
    __shared__ __align__(16) float ts[32 * 68];
    int tid = threadIdx.x;
    int p = tid >> 4, q = tid & 15;
    int a0 = p * 4, b0 = q * 4;
    size_t R0 = (size_t)blockIdx.x * 256;

    float acc[4][4];
#pragma unroll
    for (int i = 0; i < 4; i++)
#pragma unroll
        for (int j = 0; j < 4; j++) acc[i][j] = 0.f;
    float msum = 0.f;

    for (int chunk = 0; chunk < 8; chunk++) {
#pragma unroll
        for (int i = 0; i < 2; i++) {
            int idx = tid + i * 256;            // 0..511 float4s
            int row = idx >> 4, c4 = idx & 15;
            float4 v = *(const float4*)(rep + (R0 + chunk * 32 + row) * 64 + c4 * 4);
            *(float4*)(ts + row * 68 + c4 * 4) = v;
        }
        __syncthreads();
#pragma unroll 4
        for (int k = 0; k < 32; k++) {
            float4 ta = *(const float4*)(ts + k * 68 + a0);
            float4 tb = *(const float4*)(ts + k * 68 + b0);
            acc[0][0] += ta.x * tb.x; acc[0][1] += ta.x * tb.y; acc[0][2] += ta.x * tb.z; acc[0][3] += ta.x * tb.w;
            acc[1][0] += ta.y * tb.x; acc[1][1] += ta.y * tb.y; acc[1][2] += ta.y * tb.z; acc[1][3] += ta.y * tb.w;
            acc[2][0] += ta.z * tb.x; acc[2][1] += ta.z * tb.y; acc[2][2] += ta.z * tb.z; acc[2][3] += ta.z * tb.w;
            acc[3][0] += ta.w * tb.x; acc[3][1] += ta.w * tb.y; acc[3][2] += ta.w * tb.z; acc[3][3] += ta.w * tb.w;
        }
        if (tid < 64) {
#pragma unroll 8
            for (int k = 0; k < 32; k++) msum += ts[k * 68 + tid];
        }
        __syncthreads();
    }
    float* cp = g_cp + (size_t)blockIdx.x * 4096;
#pragma unroll
    for (int i = 0; i < 4; i++)
#pragma unroll
        for (int j = 0; j < 4; j++)
            cp[(a0 + i) * 64 + (b0 + j)] = acc[i][j];
    if (tid < 64) g_cm[(size_t)blockIdx.x * 64 + tid] = msum;
}

// ---------------- kernel 4a: reduce partials -> g_C, g_m  (65-block, proven) -
__global__ __launch_bounds__(256) void k4a_reduce() {
    __shared__ float red[256];
    int tid = threadIdx.x;
    int i = tid & 63, part = tid >> 6;
    int blk = blockIdx.x;
    float s = 0.f;
    if (blk < 64) {
        int idx = blk * 64 + i;
        for (int pb = part * 64; pb < part * 64 + 64; pb++)
            s += g_cp[(size_t)pb * 4096 + idx];
    } else {
        for (int pb = part * 64; pb < part * 64 + 64; pb++)
            s += g_cm[(size_t)pb * 64 + i];
    }
    red[tid] = s;
    __syncthreads();
    if (part == 0) {
        float t = red[i] + red[i + 64] + red[i + 128] + red[i + 192];
        if (blk < 64) g_C[blk * 64 + i] = t;
        else          g_m[i] = t;
    }
}

// ---------------- kernel 4b: analytic BN scale/shift per (d,b)  (proven) -----
__global__ __launch_bounds__(256) void k4b_stats(const float* __restrict__ W1,
                                                 const float* __restrict__ gamma,
                                                 const float* __restrict__ beta) {
    __shared__ float Cs[64 * 65];
    __shared__ float Ws1[4096];
    __shared__ float sm_m[64];
    __shared__ float mq[256], me[256];
    int tid = threadIdx.x;
    int b = tid & 63, part = tid >> 6;
    int d = blockIdx.x;

    for (int idx = tid; idx < 4096; idx += 256) {
        int a = idx >> 6, a2 = idx & 63;
        Cs[a * 65 + a2] = g_C[idx];
        Ws1[idx] = W1[(size_t)d * 4096 + idx];
    }
    if (tid < 64) sm_m[tid] = g_m[tid];
    __syncthreads();

    float qp = 0.f, ep = 0.f;
    int aBeg = part * 16;
#pragma unroll 2
    for (int a = aBeg; a < aBeg + 16; a++) {
        float wa = Ws1[a * 64 + b];
        float ta = 0.f;
#pragma unroll 8
        for (int a2 = 0; a2 < 64; a2++) ta += Cs[a * 65 + a2] * Ws1[a2 * 64 + b];
        qp += wa * ta;
        ep += sm_m[a] * wa;
    }
    mq[tid] = qp; me[tid] = ep;
    __syncthreads();
    if (part == 0) {
        const float invN = 1.f / 65536.f;
        float q  = mq[b] + mq[b + 64] + mq[b + 128] + mq[b + 192];
        float eg = (me[b] + me[b + 64] + me[b + 128] + me[b + 192]) * invN;
        float var = q * invN - eg * eg;
        float sc = gamma[d * 64 + b] * rsqrtf(fmaxf(var, 0.f) + 1e-5f);
        g_scale[d * 64 + b] = sc;
        g_shift[d * 64 + b] = beta[d * 64 + b] - eg * sc;
    }
}

// ---------------- kernel 5f: fused  g=rep@W1 -> BN+ELU -> y=h'@W2+b2 ---------
// R14-exact structure (no W2 register prefetch — it spilled in R15).
// Single change vs R14: expm1f -> __expf(v)-1 in the ELU.
#define HSTR 129
#define K5_DSMEM ((6144 + 64 * HSTR) * 4)
__global__ __launch_bounds__(256) void k5_fused(const float* __restrict__ rep,
                                               const float* __restrict__ W1,
                                               const float* __restrict__ W2,
                                               const float* __restrict__ b2) {
    extern __shared__ __align__(16) float dsm[];
    float* Ws = dsm;            // 6144 floats
    float* HR = dsm + 6144;     // 64*129 floats
    int tid = threadIdx.x;
    int tx = tid & 7, ty = tid >> 3;
    int d = blockIdx.y;
    int n0 = blockIdx.x * 128;

    float sc[8], sh[8];
#pragma unroll
    for (int c = 0; c < 8; c++) {
        sc[c] = g_scale[d * 64 + tx * 8 + c];
        sh[c] = g_shift[d * 64 + tx * 8 + c];
    }

    // ---- stage FULL rep tile k-major ----
#pragma unroll
    for (int half = 0; half < 2; half++) {
#pragma unroll
        for (int i = 0; i < 4; i++) {
            int l = tid + i * 256;
            int r = l >> 3, kk4 = l & 7;
            float4 v = *(const float4*)(rep + (size_t)(n0 + r) * 64 + half * 32 + kk4 * 4);
            int kb = half * 32 + kk4 * 4;
            HR[(kb + 0) * HSTR + r] = v.x;
            HR[(kb + 1) * HSTR + r] = v.y;
            HR[(kb + 2) * HSTR + r] = v.z;
            HR[(kb + 3) * HSTR + r] = v.w;
        }
    }
    // ---- stage FULL W1 ----
#pragma unroll
    for (int i = 0; i < 4; i++) {
        int l = tid + i * 256;
        *(float4*)(Ws + l * 4) = *(const float4*)(W1 + (size_t)d * 4096 + l * 4);
    }
    __syncthreads();                                   // sync #1

    float acc[4][8];
#pragma unroll
    for (int j = 0; j < 4; j++)
#pragma unroll
        for (int c = 0; c < 8; c++) acc[j][c] = 0.f;
#pragma unroll 8
    for (int kk = 0; kk < 64; kk++) {
        float ar[4];
#pragma unroll
        for (int j = 0; j < 4; j++) ar[j] = HR[kk * HSTR + ty * 4 + j];
        float4 w0 = *(const float4*)(Ws + kk * 64 + tx * 8);
        float4 w1 = *(const float4*)(Ws + kk * 64 + tx * 8 + 4);
#pragma unroll
        for (int j = 0; j < 4; j++) {
            acc[j][0] += ar[j] * w0.x; acc[j][1] += ar[j] * w0.y;
            acc[j][2] += ar[j] * w0.z; acc[j][3] += ar[j] * w0.w;
            acc[j][4] += ar[j] * w1.x; acc[j][5] += ar[j] * w1.y;
            acc[j][6] += ar[j] * w1.z; acc[j][7] += ar[j] * w1.w;
        }
    }
    __syncthreads();                                   // sync #2

    // ---- BN + fast ELU, h' k-major into HR (2-way max conflicts) ----
#pragma unroll
    for (int c = 0; c < 8; c++)
#pragma unroll
        for (int j = 0; j < 4; j++) {
            float v = acc[j][c] * sc[c] + sh[c];
            v = v > 0.f ? v : (__expf(v) - 1.f);
            HR[(tx * 8 + c) * HSTR + ty * 4 + j] = v;
        }
    // ---- stage FULL W2 (global -> smem, as in R14) ----
#pragma unroll
    for (int i = 0; i < 6; i++) {
        int l = tid + i * 256;
        *(float4*)(Ws + l * 4) = *(const float4*)(W2 + (size_t)d * 6144 + l * 4);
    }
    __syncthreads();                                   // sync #3

    int tx2 = tid & 15, ty2 = tid >> 4;
    float acc2[8][6];
#pragma unroll
    for (int j = 0; j < 8; j++)
#pragma unroll
        for (int c = 0; c < 6; c++) acc2[j][c] = 0.f;
#pragma unroll 8
    for (int kk = 0; kk < 64; kk++) {
        float ar[8];
#pragma unroll
        for (int j = 0; j < 8; j++) ar[j] = HR[kk * HSTR + ty2 * 8 + j];
        const float* wp = Ws + kk * 96 + tx2 * 6;
        float2 w0 = *(const float2*)(wp);
        float2 w1 = *(const float2*)(wp + 2);
        float2 w2v = *(const float2*)(wp + 4);
#pragma unroll
        for (int j = 0; j < 8; j++) {
            acc2[j][0] += ar[j] * w0.x;  acc2[j][1] += ar[j] * w0.y;
            acc2[j][2] += ar[j] * w1.x;  acc2[j][3] += ar[j] * w1.y;
            acc2[j][4] += ar[j] * w2v.x; acc2[j][5] += ar[j] * w2v.y;
        }
    }
    float bb[6];
#pragma unroll
    for (int c = 0; c < 6; c++) bb[c] = b2[d * 96 + tx2 * 6 + c];
#pragma unroll
    for (int j = 0; j < 8; j++) {
        int r = ty2 * 8 + j;
        float* op = g_y + (size_t)d * NROWS * 96 + (size_t)(n0 + r) * 96 + tx2 * 6;
        float2 o;
        o.x = acc2[j][0] + bb[0]; o.y = acc2[j][1] + bb[1]; *(float2*)(op)     = o;
        o.x = acc2[j][2] + bb[2]; o.y = acc2[j][3] + bb[3]; *(float2*)(op + 2) = o;
        o.x = acc2[j][4] + bb[4]; o.y = acc2[j][5] + bb[5]; *(float2*)(op + 4) = o;
    }
}

// ---------------- kernel 6: interleave, float4 everywhere  (proven) ----------
__global__ __launch_bounds__(256) void k6_interleave(float* __restrict__ out) {
    __shared__ __align__(16) float sm[8 * 772];
    int tid = threadIdx.x;
    int n0 = blockIdx.x * 8;
#pragma unroll
    for (int i = 0; i < 6; i++) {
        int idx = tid + i * 256;            // 0..1535 float4s
        int f = idx * 4;
        int d = f / 768; int m = f % 768; int n = m / 96; int p = m % 96;
        float4 v = *(const float4*)(g_y + (size_t)d * NROWS * 96 + (size_t)(n0 + n) * 96 + p);
        *(float4*)(sm + d * 772 + n * 96 + p) = v;
    }
    __syncthreads();
#pragma unroll
    for (int i = 0; i < 6; i++) {
        int idx = tid + i * 256;
        int f = idx * 4;
        int n = f / 768; int q = f % 768;
        int p = q >> 3; int dd = q & 7;
        float4 o;
        o.x = sm[(dd + 0) * 772 + n * 96 + p];
        o.y = sm[(dd + 1) * 772 + n * 96 + p];
        o.z = sm[(dd + 2) * 772 + n * 96 + p];
        o.w = sm[(dd + 3) * 772 + n * 96 + p];
        *(float4*)(out + (size_t)(n0 + n) * 768 + q) = o;
    }
}

// ---------------- launcher ----------------------------------------------------
extern "C" void kernel_launch(void* const* d_in, const int* in_sizes, int n_in,
                              void* d_out, int out_size) {
    const float* x     = (const float*)d_in[0];
    const float* B     = (const float*)d_in[1];
    const float* lw    = (const float*)d_in[2];
    const float* lb    = (const float*)d_in[3];
    const float* W1    = (const float*)d_in[4];
    // d_in[5] = b1: cancels exactly inside train-mode BatchNorm (h - mu); unused.
    const float* gamma = (const float*)d_in[6];
    const float* beta  = (const float*)d_in[7];
    const float* W2    = (const float*)d_in[8];
    const float* b2    = (const float*)d_in[9];

    float* out = (float*)d_out;
    float* rep = out + (size_t)NROWS * (PPC * DT);   // rep section after y_1

    cudaFuncSetAttribute(k1_gemm_norm, cudaFuncAttributeMaxDynamicSharedMemorySize, K1_DSMEM);
    cudaFuncSetAttribute(k5_fused, cudaFuncAttributeMaxDynamicSharedMemorySize, K5_DSMEM);

    k1_gemm_norm<<<512, 256, K1_DSMEM>>>(x, B);
    k2_window<<<512, 256>>>(lw, lb, rep);
    k3_cov<<<NBLK_COV, 256>>>(rep);
    k4a_reduce<<<65, 256>>>();
    k4b_stats<<<DT, 256>>>(W1, gamma, beta);
    k5_fused<<<dim3(512, DT), 256, K5_DSMEM>>>(rep, W1, W2, b2);
    k6_interleave<<<8192, 256>>>(out);
}